// round 15
// baseline (speedup 1.0000x reference)
#include <cuda_runtime.h>
#include <cuda_fp16.h>
#include <mma.h>
#include <math.h>
#include <stdint.h>

using namespace nvcuda;

// ---------------- problem constants (fixed shapes) ----------------
#define T_TOK   8192          // B*S
#define D_DIM   1024
#define E_EXP   8
#define H_DIM   4096
#define TOPK    2
#define PADMAX  18432         // T*K + E*255 rounded up to 256 multiple
#define MTT     (PADMAX/256)  // 72 row tiles (256 rows each)

// fp16 GEMM geometry: 256x128 block tile, K-chunk 64, 3-stage cp.async ring,
// 8 warps (4x2), warp tile 64x64, 256 threads, 1 block/SM
#define KCH     64
#define AST     72            // A smem stride (halves): 64 + 8 pad
#define BST     136           // B smem stride (halves): 128 + 8 pad
#define SAH     (256*AST)     // 18432 halves / A stage
#define SBH     (KCH*BST)     // 8704 halves / B stage
#define NST     3
#define DYN_B   (NST*(SAH+SBH)*2)   // 162816 bytes (covers 256*132*4=135168B patch)

// ---------------- device scratch (referenced ONLY in device code) ----------------
__device__ float g_probs_sum[E_EXP];
__device__ int   g_counts[E_EXP];
__device__ int   g_fill[E_EXP];
__device__ int   g_offsets[E_EXP + 1];
__device__ int   g_total_rows;
__device__ int   g_top_e[T_TOK * TOPK];
__device__ float g_top_w[T_TOK * TOPK];
__device__ int   g_row_of_tk[T_TOK * TOPK];
__device__ int   g_token_of_row[PADMAX];

__device__ __align__(16) __half g_xh [(size_t)T_TOK * D_DIM];          // 16MB
__device__ __align__(16) __half g_w1h[(size_t)E_EXP * D_DIM * H_DIM];  // 64MB
__device__ __align__(16) __half g_w2h[(size_t)E_EXP * H_DIM * D_DIM];  // 64MB
__device__ __align__(16) __half g_hsh[(size_t)PADMAX * H_DIM];         // 151MB
__device__ __align__(16) float  g_ys [(size_t)PADMAX * D_DIM];         // 75MB

// ---------------- helpers ----------------
__device__ __forceinline__ void cp16(void* dst, const void* src, int nbytes) {
    unsigned s = (unsigned)__cvta_generic_to_shared(dst);
    asm volatile("cp.async.cg.shared.global [%0], [%1], 16, %2;" :: "r"(s), "l"(src), "r"(nbytes));
}
__device__ __forceinline__ void cp_commit() {
    asm volatile("cp.async.commit_group;" ::: "memory");
}
__device__ __forceinline__ uint2 pack4h(float a, float b, float c, float d) {
    __half2 h01 = __floats2half2_rn(a, b);
    __half2 h23 = __floats2half2_rn(c, d);
    uint2 u;
    u.x = *(uint32_t*)&h01;
    u.y = *(uint32_t*)&h23;
    return u;
}

// ---------------- fp32 -> fp16 conversion into device scratch ----------------
__global__ __launch_bounds__(256) void conv_kernel(const float* __restrict__ src,
                                                   int n4, int which) {
    __half* dst = (which == 0) ? g_xh : (which == 1) ? g_w1h : g_w2h;
    int i = blockIdx.x * 256 + threadIdx.x;
    if (i >= n4) return;
    float4 v = ((const float4*)src)[i];
    ((uint2*)dst)[i] = pack4h(v.x, v.y, v.z, v.w);
}

// ---------------- init: counters + padding rows ----------------
__global__ void init_kernel() {
    int i = blockIdx.x * 256 + threadIdx.x;
    if (i < PADMAX) g_token_of_row[i] = -1;
    if (i < E_EXP) { g_probs_sum[i] = 0.0f; g_counts[i] = 0; g_fill[i] = 0; }
}

// ---------------- router: 1 warp per token ----------------
__global__ __launch_bounds__(256) void router_kernel(
    const float* __restrict__ x, const float* __restrict__ rw,
    const float* __restrict__ rb)
{
    const int warp = threadIdx.x >> 5;
    const int lane = threadIdx.x & 31;
    const int t = blockIdx.x * 8 + warp;

    __shared__ float sp[E_EXP];
    if (threadIdx.x < E_EXP) sp[threadIdx.x] = 0.0f;
    __syncthreads();

    float acc[E_EXP];
    #pragma unroll
    for (int e = 0; e < E_EXP; ++e) acc[e] = 0.0f;

    const float* xr = x + (size_t)t * D_DIM;
    const float4* rw4 = (const float4*)rw;   // router_w [D, E=8] row-major
    for (int d = lane; d < D_DIM; d += 32) {
        float xv = xr[d];
        float4 r0 = rw4[d * 2];
        float4 r1 = rw4[d * 2 + 1];
        acc[0] += xv * r0.x; acc[1] += xv * r0.y; acc[2] += xv * r0.z; acc[3] += xv * r0.w;
        acc[4] += xv * r1.x; acc[5] += xv * r1.y; acc[6] += xv * r1.z; acc[7] += xv * r1.w;
    }
    #pragma unroll
    for (int off = 16; off > 0; off >>= 1) {
        #pragma unroll
        for (int e = 0; e < E_EXP; ++e)
            acc[e] += __shfl_xor_sync(0xFFFFFFFFu, acc[e], off);
    }

    if (lane == 0) {
        float p[E_EXP];
        float m = -1e30f;
        #pragma unroll
        for (int e = 0; e < E_EXP; ++e) { p[e] = acc[e] + rb[e]; m = fmaxf(m, p[e]); }
        float s = 0.0f;
        #pragma unroll
        for (int e = 0; e < E_EXP; ++e) { p[e] = expf(p[e] - m); s += p[e]; }
        float inv = 1.0f / s;
        #pragma unroll
        for (int e = 0; e < E_EXP; ++e) {
            p[e] *= inv;
            atomicAdd(&sp[e], p[e]);
        }
        // top-2 (strict > keeps lowest index on ties, matching lax.top_k)
        int i1 = 0;
        #pragma unroll
        for (int e = 1; e < E_EXP; ++e) if (p[e] > p[i1]) i1 = e;
        int i2 = (i1 == 0) ? 1 : 0;
        #pragma unroll
        for (int e = 0; e < E_EXP; ++e) if (e != i1 && p[e] > p[i2]) i2 = e;
        float inv2 = 1.0f / (p[i1] + p[i2]);
        g_top_e[2 * t]     = i1;  g_top_w[2 * t]     = p[i1] * inv2;
        g_top_e[2 * t + 1] = i2;  g_top_w[2 * t + 1] = p[i2] * inv2;
        atomicAdd(&g_counts[i1], 1);
        atomicAdd(&g_counts[i2], 1);
    }
    __syncthreads();
    if (threadIdx.x < E_EXP) atomicAdd(&g_probs_sum[threadIdx.x], sp[threadIdx.x]);
}

// ---------------- offsets (padded to 256) + load-balance loss ----------------
__global__ void offsets_kernel(float* __restrict__ out, int out_n) {
    if (threadIdx.x == 0) {
        int off = 0;
        #pragma unroll
        for (int e = 0; e < E_EXP; ++e) {
            g_offsets[e] = off;
            off += ((g_counts[e] + 255) >> 8) << 8;
        }
        g_offsets[E_EXP] = off;
        g_total_rows = off;
        float loss = 0.0f;
        #pragma unroll
        for (int e = 0; e < E_EXP; ++e) {
            float mp = g_probs_sum[e] * (1.0f / (float)T_TOK);
            loss += mp * logf(mp);
        }
        out[out_n - 1] = (float)E_EXP * loss;
    }
}

// ---------------- scatter tokens into per-expert segments ----------------
__global__ void scatter_kernel() {
    int t = blockIdx.x * 256 + threadIdx.x;
    if (t >= T_TOK) return;
    #pragma unroll
    for (int k = 0; k < TOPK; ++k) {
        int e = g_top_e[2 * t + k];
        int pos = g_offsets[e] + atomicAdd(&g_fill[e], 1);
        g_token_of_row[pos] = t;
        g_row_of_tk[2 * t + k] = pos;
    }
}

// ---------------- grouped GEMM1: hsh = gelu(gather(xh) @ w1h + b1) ----------------
// 256x128x64 block tile, 3-stage cp.async ring, fp16 WMMA m16n16k16,
// 8 warps (4x2), warp tile 64x64, one __syncthreads per k-iter.
__global__ __launch_bounds__(256, 1) void gemm1_kernel(const float* __restrict__ B1)
{
    extern __shared__ __align__(16) char dyn[];
    const int row0 = blockIdx.y * 256;
    if (row0 >= g_total_rows) return;
    const int n0 = blockIdx.x * 128;

    int e = 0;
    #pragma unroll
    for (int i = 0; i < E_EXP - 1; ++i) if (g_offsets[i + 1] <= row0) e = i + 1;
    const __half* We = g_w1h + (size_t)e * D_DIM * H_DIM;   // [K=1024, H]
    const float* be = B1 + e * H_DIM;

    __half* Ab = (__half*)dyn;                  // [3][SAH]
    __half* Bb = (__half*)dyn + NST * SAH;      // [3][SBH]
    __shared__ int s_tok[256];

    const int tid = threadIdx.x;
    s_tok[tid] = g_token_of_row[row0 + tid];
    __syncthreads();

    wmma::fragment<wmma::accumulator, 16, 16, 16, float> cf[4][4];
    #pragma unroll
    for (int i = 0; i < 4; ++i)
        #pragma unroll
        for (int j = 0; j < 4; ++j) wmma::fill_fragment(cf[i][j], 0.0f);

    const int warp = tid >> 5;
    const int wrow = (warp >> 1) * 64;     // 0,64,128,192
    const int wcol = (warp & 1) * 64;      // 0,64

    // loader coords (256 threads): A 256r x 64h -> 2048 8h-chunks (8/thread)
    const int arw = tid >> 3, acl = (tid & 7) << 3;    // A row +32/step
    const int brw = tid >> 4, bcl = (tid & 15) << 3;   // B row +16/step

    // ---- prologue: stages 0,1 ----
    #pragma unroll
    for (int ps = 0; ps < 2; ++ps) {
        const int k0 = ps * KCH;
        __half* Ad = Ab + ps * SAH;
        __half* Bd = Bb + ps * SBH;
        #pragma unroll
        for (int i = 0; i < 8; ++i) {
            int r = arw + i * 32;
            int tok = s_tok[r];
            cp16(Ad + r * AST + acl,
                 g_xh + (size_t)(tok < 0 ? 0 : tok) * D_DIM + k0 + acl,
                 tok < 0 ? 0 : 16);
        }
        #pragma unroll
        for (int i = 0; i < 4; ++i) {
            int r = brw + i * 16;
            cp16(Bd + r * BST + bcl, We + (size_t)(k0 + r) * H_DIM + n0 + bcl, 16);
        }
        cp_commit();
    }

    const int KT = D_DIM / KCH;   // 16
    for (int kt = 0; kt < KT; ++kt) {
        if (kt + 1 < KT) asm volatile("cp.async.wait_group 1;" ::: "memory");
        else             asm volatile("cp.async.wait_group 0;" ::: "memory");
        __syncthreads();   // stage kt visible; stage (kt+2)%3 free to refill

        if (kt + 2 < KT) {
            const int k0 = (kt + 2) * KCH;
            const int s = (kt + 2) % NST;
            __half* Ad = Ab + s * SAH;
            __half* Bd = Bb + s * SBH;
            #pragma unroll
            for (int i = 0; i < 8; ++i) {
                int r = arw + i * 32;
                int tok = s_tok[r];
                cp16(Ad + r * AST + acl,
                     g_xh + (size_t)(tok < 0 ? 0 : tok) * D_DIM + k0 + acl,
                     tok < 0 ? 0 : 16);
            }
            #pragma unroll
            for (int i = 0; i < 4; ++i) {
                int r = brw + i * 16;
                cp16(Bd + r * BST + bcl, We + (size_t)(k0 + r) * H_DIM + n0 + bcl, 16);
            }
            cp_commit();
        }

        const __half* Ac = Ab + (kt % NST) * SAH;
        const __half* Bc = Bb + (kt % NST) * SBH;
        #pragma unroll
        for (int kk = 0; kk < KCH; kk += 16) {
            wmma::fragment<wmma::matrix_a, 16, 16, 16, __half, wmma::row_major> af[4];
            wmma::fragment<wmma::matrix_b, 16, 16, 16, __half, wmma::row_major> bf[4];
            #pragma unroll
            for (int i = 0; i < 4; ++i)
                wmma::load_matrix_sync(af[i], Ac + (wrow + i * 16) * AST + kk, AST);
            #pragma unroll
            for (int j = 0; j < 4; ++j)
                wmma::load_matrix_sync(bf[j], Bc + kk * BST + wcol + j * 16, BST);
            #pragma unroll
            for (int i = 0; i < 4; ++i)
                #pragma unroll
                for (int j = 0; j < 4; ++j)
                    wmma::mma_sync(cf[i][j], af[i], bf[j], cf[i][j]);
        }
    }
    __syncthreads();   // all compute done before dyn reuse as patch

    // ---- epilogue: fp32 patch, bias + exact GELU, fp16 coalesced store ----
    float* patch = (float*)dyn;   // 256*132 fp32 = 135168B <= DYN_B
    #pragma unroll
    for (int i = 0; i < 4; ++i)
        #pragma unroll
        for (int j = 0; j < 4; ++j)
            wmma::store_matrix_sync(patch + (wrow + i * 16) * 132 + wcol + j * 16,
                                    cf[i][j], 132, wmma::mem_row_major);
    __syncthreads();

    const int ec = (tid & 31) << 2;                 // fixed column per thread
    const float4 bv = *(const float4*)(be + n0 + ec);
    #pragma unroll
    for (int k = 0; k < 32; ++k) {
        int r = (tid >> 5) + k * 8;                  // 0..255
        float4 v = *(const float4*)(patch + r * 132 + ec);
        v.x += bv.x; v.y += bv.y; v.z += bv.z; v.w += bv.w;
        v.x = 0.5f * v.x * (1.0f + erff(v.x * 0.70710678118654752f));
        v.y = 0.5f * v.y * (1.0f + erff(v.y * 0.70710678118654752f));
        v.z = 0.5f * v.z * (1.0f + erff(v.z * 0.70710678118654752f));
        v.w = 0.5f * v.w * (1.0f + erff(v.w * 0.70710678118654752f));
        *(uint2*)(g_hsh + (size_t)(row0 + r) * H_DIM + n0 + ec) = pack4h(v.x, v.y, v.z, v.w);
    }
}

// ---------------- grouped GEMM2: ys[row] = hsh[row] @ w2h[e] + b2[e] ----------------
__global__ __launch_bounds__(256, 1) void gemm2_kernel(const float* __restrict__ B2)
{
    extern __shared__ __align__(16) char dyn[];
    const int row0 = blockIdx.y * 256;
    if (row0 >= g_total_rows) return;
    const int n0 = blockIdx.x * 128;

    int e = 0;
    #pragma unroll
    for (int i = 0; i < E_EXP - 1; ++i) if (g_offsets[i + 1] <= row0) e = i + 1;
    const __half* We = g_w2h + (size_t)e * H_DIM * D_DIM;   // [K=4096, D]
    const float* be = B2 + e * D_DIM;

    __half* Ab = (__half*)dyn;
    __half* Bb = (__half*)dyn + NST * SAH;

    const int tid = threadIdx.x;

    wmma::fragment<wmma::accumulator, 16, 16, 16, float> cf[4][4];
    #pragma unroll
    for (int i = 0; i < 4; ++i)
        #pragma unroll
        for (int j = 0; j < 4; ++j) wmma::fill_fragment(cf[i][j], 0.0f);

    const int warp = tid >> 5;
    const int wrow = (warp >> 1) * 64;
    const int wcol = (warp & 1) * 64;
    const int arw = tid >> 3, acl = (tid & 7) << 3;
    const int brw = tid >> 4, bcl = (tid & 15) << 3;

    // ---- prologue: stages 0,1 ----
    #pragma unroll
    for (int ps = 0; ps < 2; ++ps) {
        const int k0 = ps * KCH;
        __half* Ad = Ab + ps * SAH;
        __half* Bd = Bb + ps * SBH;
        #pragma unroll
        for (int i = 0; i < 8; ++i) {
            int r = arw + i * 32;
            cp16(Ad + r * AST + acl, g_hsh + (size_t)(row0 + r) * H_DIM + k0 + acl, 16);
        }
        #pragma unroll
        for (int i = 0; i < 4; ++i) {
            int r = brw + i * 16;
            cp16(Bd + r * BST + bcl, We + (size_t)(k0 + r) * D_DIM + n0 + bcl, 16);
        }
        cp_commit();
    }

    const int KT = H_DIM / KCH;   // 64
    for (int kt = 0; kt < KT; ++kt) {
        if (kt + 1 < KT) asm volatile("cp.async.wait_group 1;" ::: "memory");
        else             asm volatile("cp.async.wait_group 0;" ::: "memory");
        __syncthreads();

        if (kt + 2 < KT) {
            const int k0 = (kt + 2) * KCH;
            const int s = (kt + 2) % NST;
            __half* Ad = Ab + s * SAH;
            __half* Bd = Bb + s * SBH;
            #pragma unroll
            for (int i = 0; i < 8; ++i) {
                int r = arw + i * 32;
                cp16(Ad + r * AST + acl, g_hsh + (size_t)(row0 + r) * H_DIM + k0 + acl, 16);
            }
            #pragma unroll
            for (int i = 0; i < 4; ++i) {
                int r = brw + i * 16;
                cp16(Bd + r * BST + bcl, We + (size_t)(k0 + r) * D_DIM + n0 + bcl, 16);
            }
            cp_commit();
        }

        const __half* Ac = Ab + (kt % NST) * SAH;
        const __half* Bc = Bb + (kt % NST) * SBH;
        #pragma unroll
        for (int kk = 0; kk < KCH; kk += 16) {
            wmma::fragment<wmma::matrix_a, 16, 16, 16, __half, wmma::row_major> af[4];
            wmma::fragment<wmma::matrix_b, 16, 16, 16, __half, wmma::row_major> bf[4];
            #pragma unroll
            for (int i = 0; i < 4; ++i)
                wmma::load_matrix_sync(af[i], Ac + (wrow + i * 16) * AST + kk, AST);
            #pragma unroll
            for (int j = 0; j < 4; ++j)
                wmma::load_matrix_sync(bf[j], Bc + kk * BST + wcol + j * 16, BST);
            #pragma unroll
            for (int i = 0; i < 4; ++i)
                #pragma unroll
                for (int j = 0; j < 4; ++j)
                    wmma::mma_sync(cf[i][j], af[i], bf[j], cf[i][j]);
        }
    }
    __syncthreads();

    // ---- epilogue: bias, fp32 coalesced store to g_ys ----
    float* patch = (float*)dyn;
    #pragma unroll
    for (int i = 0; i < 4; ++i)
        #pragma unroll
        for (int j = 0; j < 4; ++j)
            wmma::store_matrix_sync(patch + (wrow + i * 16) * 132 + wcol + j * 16,
                                    cf[i][j], 132, wmma::mem_row_major);
    __syncthreads();

    const int ec = (tid & 31) << 2;
    const float4 bv = *(const float4*)(be + n0 + ec);
    #pragma unroll
    for (int k = 0; k < 32; ++k) {
        int r = (tid >> 5) + k * 8;
        float4 v = *(const float4*)(patch + r * 132 + ec);
        v.x += bv.x; v.y += bv.y; v.z += bv.z; v.w += bv.w;
        *(float4*)(g_ys + (size_t)(row0 + r) * D_DIM + n0 + ec) = v;
    }
}

// ---------------- combine: out[t] = w0*ys[r0] + w1*ys[r1] ----------------
__global__ __launch_bounds__(256) void combine_kernel(float* __restrict__ out) {
    int i = blockIdx.x * 256 + threadIdx.x;      // over T*D/4 float4
    int t = i >> 8;                              // D/4 = 256 float4 per token
    int c = i & 255;
    int r0 = g_row_of_tk[2 * t], r1 = g_row_of_tk[2 * t + 1];
    float w0 = g_top_w[2 * t],   w1 = g_top_w[2 * t + 1];
    const float4* y4 = (const float4*)g_ys;
    float4 a = y4[(size_t)r0 * 256 + c];
    float4 b = y4[(size_t)r1 * 256 + c];
    float4 o;
    o.x = w0 * a.x + w1 * b.x;
    o.y = w0 * a.y + w1 * b.y;
    o.z = w0 * a.z + w1 * b.z;
    o.w = w0 * a.w + w1 * b.w;
    ((float4*)out)[i] = o;
}

// ---------------- launch ----------------
extern "C" void kernel_launch(void* const* d_in, const int* in_sizes, int n_in,
                              void* d_out, int out_size) {
    const float* x  = (const float*)d_in[0];
    const float* rw = (const float*)d_in[1];
    const float* rb = (const float*)d_in[2];
    const float* w1 = (const float*)d_in[3];
    const float* b1 = (const float*)d_in[4];
    const float* w2 = (const float*)d_in[5];
    const float* b2 = (const float*)d_in[6];
    float* out = (float*)d_out;

    static int attr_done = 0;
    if (!attr_done) {
        cudaFuncSetAttribute(gemm1_kernel, cudaFuncAttributeMaxDynamicSharedMemorySize, DYN_B);
        cudaFuncSetAttribute(gemm2_kernel, cudaFuncAttributeMaxDynamicSharedMemorySize, DYN_B);
        attr_done = 1;
    }

    init_kernel<<<(PADMAX + 255) / 256, 256>>>();
    router_kernel<<<T_TOK / 8, 256>>>(x, rw, rb);
    offsets_kernel<<<1, 32>>>(out, out_size);
    scatter_kernel<<<(T_TOK + 255) / 256, 256>>>();

    // fp32 -> fp16 operand conversion (dst selected inside kernel, NOT host-passed)
    conv_kernel<<<(T_TOK * D_DIM / 4 + 255) / 256, 256>>>(x,  T_TOK * D_DIM / 4, 0);
    conv_kernel<<<(E_EXP * D_DIM * H_DIM / 4 + 255) / 256, 256>>>(w1, E_EXP * D_DIM * H_DIM / 4, 1);
    conv_kernel<<<(E_EXP * H_DIM * D_DIM / 4 + 255) / 256, 256>>>(w2, E_EXP * H_DIM * D_DIM / 4, 2);

    gemm1_kernel<<<dim3(H_DIM / 128, MTT), 256, DYN_B>>>(b1);
    gemm2_kernel<<<dim3(D_DIM / 128, MTT), 256, DYN_B>>>(b2);
    combine_kernel<<<T_TOK, 256>>>(out);
}

// round 16
// speedup vs baseline: 1.2106x; 1.2106x over previous
#include <cuda_runtime.h>
#include <cuda_fp16.h>
#include <mma.h>
#include <math.h>
#include <stdint.h>

using namespace nvcuda;

// ---------------- problem constants (fixed shapes) ----------------
#define T_TOK   8192          // B*S
#define D_DIM   1024
#define E_EXP   8
#define H_DIM   4096
#define TOPK    2
#define PADMAX  17408         // T*K + E*127 rounded up to 128 multiple
#define MT      (PADMAX/128)  // 136 row tiles

// fp16 GEMM geometry: 128x128 block tile, K-chunk 64, 3-stage cp.async ring,
// 4 warps (2x2), warp tile 64x64, 128 threads, 2 blocks/SM  (proven R14 config)
#define KCH     64
#define AST     72            // A smem stride (halves): 64 + 8 pad
#define BST     136           // B smem stride (halves): 128 + 8 pad
#define SAH     (128*AST)     // 9216 halves / A stage
#define SBH     (KCH*BST)     // 8704 halves / B stage
#define NST     3
#define DYN_B   (NST*(SAH+SBH)*2)   // 107520 bytes (covers 67584B fp32 patch too)

// ---------------- device scratch (referenced ONLY in device code) ----------------
__device__ float g_probs_sum[E_EXP];
__device__ int   g_counts[E_EXP];
__device__ int   g_fill[E_EXP];
__device__ int   g_offsets[E_EXP + 1];
__device__ int   g_total_rows;
__device__ int   g_top_e[T_TOK * TOPK];
__device__ float g_top_w[T_TOK * TOPK];
__device__ int   g_row_of_tk[T_TOK * TOPK];
__device__ int   g_token_of_row[PADMAX];

__device__ __align__(16) __half g_xh [(size_t)T_TOK * D_DIM];          // 16MB
__device__ __align__(16) __half g_w1h[(size_t)E_EXP * D_DIM * H_DIM];  // 64MB
__device__ __align__(16) __half g_w2h[(size_t)E_EXP * H_DIM * D_DIM];  // 64MB
__device__ __align__(16) __half g_hsh[(size_t)PADMAX * H_DIM];         // 143MB
__device__ __align__(16) __half g_ysh[(size_t)PADMAX * D_DIM];         // 37MB (fp16 now)

// ---------------- helpers ----------------
__device__ __forceinline__ void cp16(void* dst, const void* src, int nbytes) {
    unsigned s = (unsigned)__cvta_generic_to_shared(dst);
    asm volatile("cp.async.cg.shared.global [%0], [%1], 16, %2;" :: "r"(s), "l"(src), "r"(nbytes));
}
__device__ __forceinline__ void cp_commit() {
    asm volatile("cp.async.commit_group;" ::: "memory");
}
__device__ __forceinline__ uint2 pack4h(float a, float b, float c, float d) {
    __half2 h01 = __floats2half2_rn(a, b);
    __half2 h23 = __floats2half2_rn(c, d);
    uint2 u;
    u.x = *(uint32_t*)&h01;
    u.y = *(uint32_t*)&h23;
    return u;
}

// ---------------- fp32 -> fp16 conversion into device scratch ----------------
__global__ __launch_bounds__(256) void conv_kernel(const float* __restrict__ src,
                                                   int n4, int which) {
    __half* dst = (which == 0) ? g_xh : (which == 1) ? g_w1h : g_w2h;
    int i = blockIdx.x * 256 + threadIdx.x;
    if (i >= n4) return;
    float4 v = ((const float4*)src)[i];
    ((uint2*)dst)[i] = pack4h(v.x, v.y, v.z, v.w);
}

// ---------------- init: counters + padding rows ----------------
__global__ void init_kernel() {
    int i = blockIdx.x * 256 + threadIdx.x;
    if (i < PADMAX) g_token_of_row[i] = -1;
    if (i < E_EXP) { g_probs_sum[i] = 0.0f; g_counts[i] = 0; g_fill[i] = 0; }
}

// ---------------- router: 1 warp per token ----------------
__global__ __launch_bounds__(256) void router_kernel(
    const float* __restrict__ x, const float* __restrict__ rw,
    const float* __restrict__ rb)
{
    const int warp = threadIdx.x >> 5;
    const int lane = threadIdx.x & 31;
    const int t = blockIdx.x * 8 + warp;

    __shared__ float sp[E_EXP];
    if (threadIdx.x < E_EXP) sp[threadIdx.x] = 0.0f;
    __syncthreads();

    float acc[E_EXP];
    #pragma unroll
    for (int e = 0; e < E_EXP; ++e) acc[e] = 0.0f;

    const float* xr = x + (size_t)t * D_DIM;
    const float4* rw4 = (const float4*)rw;   // router_w [D, E=8] row-major
    for (int d = lane; d < D_DIM; d += 32) {
        float xv = xr[d];
        float4 r0 = rw4[d * 2];
        float4 r1 = rw4[d * 2 + 1];
        acc[0] += xv * r0.x; acc[1] += xv * r0.y; acc[2] += xv * r0.z; acc[3] += xv * r0.w;
        acc[4] += xv * r1.x; acc[5] += xv * r1.y; acc[6] += xv * r1.z; acc[7] += xv * r1.w;
    }
    #pragma unroll
    for (int off = 16; off > 0; off >>= 1) {
        #pragma unroll
        for (int e = 0; e < E_EXP; ++e)
            acc[e] += __shfl_xor_sync(0xFFFFFFFFu, acc[e], off);
    }

    if (lane == 0) {
        float p[E_EXP];
        float m = -1e30f;
        #pragma unroll
        for (int e = 0; e < E_EXP; ++e) { p[e] = acc[e] + rb[e]; m = fmaxf(m, p[e]); }
        float s = 0.0f;
        #pragma unroll
        for (int e = 0; e < E_EXP; ++e) { p[e] = expf(p[e] - m); s += p[e]; }
        float inv = 1.0f / s;
        #pragma unroll
        for (int e = 0; e < E_EXP; ++e) {
            p[e] *= inv;
            atomicAdd(&sp[e], p[e]);
        }
        // top-2 (strict > keeps lowest index on ties, matching lax.top_k)
        int i1 = 0;
        #pragma unroll
        for (int e = 1; e < E_EXP; ++e) if (p[e] > p[i1]) i1 = e;
        int i2 = (i1 == 0) ? 1 : 0;
        #pragma unroll
        for (int e = 0; e < E_EXP; ++e) if (e != i1 && p[e] > p[i2]) i2 = e;
        float inv2 = 1.0f / (p[i1] + p[i2]);
        g_top_e[2 * t]     = i1;  g_top_w[2 * t]     = p[i1] * inv2;
        g_top_e[2 * t + 1] = i2;  g_top_w[2 * t + 1] = p[i2] * inv2;
        atomicAdd(&g_counts[i1], 1);
        atomicAdd(&g_counts[i2], 1);
    }
    __syncthreads();
    if (threadIdx.x < E_EXP) atomicAdd(&g_probs_sum[threadIdx.x], sp[threadIdx.x]);
}

// ---------------- offsets (padded to 128) + load-balance loss ----------------
__global__ void offsets_kernel(float* __restrict__ out, int out_n) {
    if (threadIdx.x == 0) {
        int off = 0;
        #pragma unroll
        for (int e = 0; e < E_EXP; ++e) {
            g_offsets[e] = off;
            off += ((g_counts[e] + 127) >> 7) << 7;
        }
        g_offsets[E_EXP] = off;
        g_total_rows = off;
        float loss = 0.0f;
        #pragma unroll
        for (int e = 0; e < E_EXP; ++e) {
            float mp = g_probs_sum[e] * (1.0f / (float)T_TOK);
            loss += mp * logf(mp);
        }
        out[out_n - 1] = (float)E_EXP * loss;
    }
}

// ---------------- scatter tokens into per-expert segments ----------------
__global__ void scatter_kernel() {
    int t = blockIdx.x * 256 + threadIdx.x;
    if (t >= T_TOK) return;
    #pragma unroll
    for (int k = 0; k < TOPK; ++k) {
        int e = g_top_e[2 * t + k];
        int pos = g_offsets[e] + atomicAdd(&g_fill[e], 1);
        g_token_of_row[pos] = t;
        g_row_of_tk[2 * t + k] = pos;
    }
}

// ---------------- grouped GEMM1: hsh = gelu(gather(xh) @ w1h + b1) ----------------
// 128x128x64 block tile, 3-stage cp.async ring, fp16 WMMA m16n16k16,
// 4 warps (2x2), warp tile 64x64, one __syncthreads per k-iter.
__global__ __launch_bounds__(128, 2) void gemm1_kernel(const float* __restrict__ B1)
{
    extern __shared__ __align__(16) char dyn[];
    const int row0 = blockIdx.y * 128;
    if (row0 >= g_total_rows) return;
    const int n0 = blockIdx.x * 128;

    int e = 0;
    #pragma unroll
    for (int i = 0; i < E_EXP - 1; ++i) if (g_offsets[i + 1] <= row0) e = i + 1;
    const __half* We = g_w1h + (size_t)e * D_DIM * H_DIM;   // [K=1024, H]
    const float* be = B1 + e * H_DIM;

    __half* Ab = (__half*)dyn;                  // [3][SAH]
    __half* Bb = (__half*)dyn + NST * SAH;      // [3][SBH]
    __shared__ int s_tok[128];

    const int tid = threadIdx.x;
    if (tid < 128) s_tok[tid] = g_token_of_row[row0 + tid];
    __syncthreads();

    wmma::fragment<wmma::accumulator, 16, 16, 16, float> cf[4][4];
    #pragma unroll
    for (int i = 0; i < 4; ++i)
        #pragma unroll
        for (int j = 0; j < 4; ++j) wmma::fill_fragment(cf[i][j], 0.0f);

    const int warp = tid >> 5;
    const int wrow = (warp >> 1) * 64;
    const int wcol = (warp & 1) * 64;

    // loader coords (128 threads): A 128r x 64h -> 1024 8h-chunks (8/thread)
    const int arw = tid >> 3, acl = (tid & 7) << 3;    // A row +16/step
    const int brw = tid >> 4, bcl = (tid & 15) << 3;   // B row +8/step

    // ---- prologue: stages 0,1 ----
    #pragma unroll
    for (int ps = 0; ps < 2; ++ps) {
        const int k0 = ps * KCH;
        __half* Ad = Ab + ps * SAH;
        __half* Bd = Bb + ps * SBH;
        #pragma unroll
        for (int i = 0; i < 8; ++i) {
            int r = arw + i * 16;
            int tok = s_tok[r];
            cp16(Ad + r * AST + acl,
                 g_xh + (size_t)(tok < 0 ? 0 : tok) * D_DIM + k0 + acl,
                 tok < 0 ? 0 : 16);
        }
        #pragma unroll
        for (int i = 0; i < 8; ++i) {
            int r = brw + i * 8;
            cp16(Bd + r * BST + bcl, We + (size_t)(k0 + r) * H_DIM + n0 + bcl, 16);
        }
        cp_commit();
    }

    const int KT = D_DIM / KCH;   // 16
    for (int kt = 0; kt < KT; ++kt) {
        if (kt + 1 < KT) asm volatile("cp.async.wait_group 1;" ::: "memory");
        else             asm volatile("cp.async.wait_group 0;" ::: "memory");
        __syncthreads();   // stage kt visible to all; stage (kt+2)%3 free to refill

        if (kt + 2 < KT) {
            const int k0 = (kt + 2) * KCH;
            const int s = (kt + 2) % NST;
            __half* Ad = Ab + s * SAH;
            __half* Bd = Bb + s * SBH;
            #pragma unroll
            for (int i = 0; i < 8; ++i) {
                int r = arw + i * 16;
                int tok = s_tok[r];
                cp16(Ad + r * AST + acl,
                     g_xh + (size_t)(tok < 0 ? 0 : tok) * D_DIM + k0 + acl,
                     tok < 0 ? 0 : 16);
            }
            #pragma unroll
            for (int i = 0; i < 8; ++i) {
                int r = brw + i * 8;
                cp16(Bd + r * BST + bcl, We + (size_t)(k0 + r) * H_DIM + n0 + bcl, 16);
            }
            cp_commit();
        }

        const __half* Ac = Ab + (kt % NST) * SAH;
        const __half* Bc = Bb + (kt % NST) * SBH;
        #pragma unroll
        for (int kk = 0; kk < KCH; kk += 16) {
            wmma::fragment<wmma::matrix_a, 16, 16, 16, __half, wmma::row_major> af[4];
            wmma::fragment<wmma::matrix_b, 16, 16, 16, __half, wmma::row_major> bf[4];
            #pragma unroll
            for (int i = 0; i < 4; ++i)
                wmma::load_matrix_sync(af[i], Ac + (wrow + i * 16) * AST + kk, AST);
            #pragma unroll
            for (int j = 0; j < 4; ++j)
                wmma::load_matrix_sync(bf[j], Bc + kk * BST + wcol + j * 16, BST);
            #pragma unroll
            for (int i = 0; i < 4; ++i)
                #pragma unroll
                for (int j = 0; j < 4; ++j)
                    wmma::mma_sync(cf[i][j], af[i], bf[j], cf[i][j]);
        }
    }
    __syncthreads();   // all compute done before dyn reuse as patch

    // ---- epilogue: fp32 patch, bias + exact GELU, fp16 coalesced store ----
    float* patch = (float*)dyn;   // 128*132 fp32 = 67584B <= DYN_B
    #pragma unroll
    for (int i = 0; i < 4; ++i)
        #pragma unroll
        for (int j = 0; j < 4; ++j)
            wmma::store_matrix_sync(patch + (wrow + i * 16) * 132 + wcol + j * 16,
                                    cf[i][j], 132, wmma::mem_row_major);
    __syncthreads();

    const int ec = (tid & 31) << 2;                 // fixed column per thread
    const float4 bv = *(const float4*)(be + n0 + ec);
    #pragma unroll
    for (int k = 0; k < 32; ++k) {
        int r = (tid >> 5) + k * 4;
        float4 v = *(const float4*)(patch + r * 132 + ec);
        v.x += bv.x; v.y += bv.y; v.z += bv.z; v.w += bv.w;
        v.x = 0.5f * v.x * (1.0f + erff(v.x * 0.70710678118654752f));
        v.y = 0.5f * v.y * (1.0f + erff(v.y * 0.70710678118654752f));
        v.z = 0.5f * v.z * (1.0f + erff(v.z * 0.70710678118654752f));
        v.w = 0.5f * v.w * (1.0f + erff(v.w * 0.70710678118654752f));
        *(uint2*)(g_hsh + (size_t)(row0 + r) * H_DIM + n0 + ec) = pack4h(v.x, v.y, v.z, v.w);
    }
}

// ---------------- grouped GEMM2: ysh[row] = hsh[row] @ w2h[e] + b2[e] ----------------
__global__ __launch_bounds__(128, 2) void gemm2_kernel(const float* __restrict__ B2)
{
    extern __shared__ __align__(16) char dyn[];
    const int row0 = blockIdx.y * 128;
    if (row0 >= g_total_rows) return;
    const int n0 = blockIdx.x * 128;

    int e = 0;
    #pragma unroll
    for (int i = 0; i < E_EXP - 1; ++i) if (g_offsets[i + 1] <= row0) e = i + 1;
    const __half* We = g_w2h + (size_t)e * H_DIM * D_DIM;   // [K=4096, D]
    const float* be = B2 + e * D_DIM;

    __half* Ab = (__half*)dyn;
    __half* Bb = (__half*)dyn + NST * SAH;

    const int tid = threadIdx.x;

    wmma::fragment<wmma::accumulator, 16, 16, 16, float> cf[4][4];
    #pragma unroll
    for (int i = 0; i < 4; ++i)
        #pragma unroll
        for (int j = 0; j < 4; ++j) wmma::fill_fragment(cf[i][j], 0.0f);

    const int warp = tid >> 5;
    const int wrow = (warp >> 1) * 64;
    const int wcol = (warp & 1) * 64;
    const int arw = tid >> 3, acl = (tid & 7) << 3;
    const int brw = tid >> 4, bcl = (tid & 15) << 3;

    // ---- prologue: stages 0,1 ----
    #pragma unroll
    for (int ps = 0; ps < 2; ++ps) {
        const int k0 = ps * KCH;
        __half* Ad = Ab + ps * SAH;
        __half* Bd = Bb + ps * SBH;
        #pragma unroll
        for (int i = 0; i < 8; ++i) {
            int r = arw + i * 16;
            cp16(Ad + r * AST + acl, g_hsh + (size_t)(row0 + r) * H_DIM + k0 + acl, 16);
        }
        #pragma unroll
        for (int i = 0; i < 8; ++i) {
            int r = brw + i * 8;
            cp16(Bd + r * BST + bcl, We + (size_t)(k0 + r) * D_DIM + n0 + bcl, 16);
        }
        cp_commit();
    }

    const int KT = H_DIM / KCH;   // 64
    for (int kt = 0; kt < KT; ++kt) {
        if (kt + 1 < KT) asm volatile("cp.async.wait_group 1;" ::: "memory");
        else             asm volatile("cp.async.wait_group 0;" ::: "memory");
        __syncthreads();

        if (kt + 2 < KT) {
            const int k0 = (kt + 2) * KCH;
            const int s = (kt + 2) % NST;
            __half* Ad = Ab + s * SAH;
            __half* Bd = Bb + s * SBH;
            #pragma unroll
            for (int i = 0; i < 8; ++i) {
                int r = arw + i * 16;
                cp16(Ad + r * AST + acl, g_hsh + (size_t)(row0 + r) * H_DIM + k0 + acl, 16);
            }
            #pragma unroll
            for (int i = 0; i < 8; ++i) {
                int r = brw + i * 8;
                cp16(Bd + r * BST + bcl, We + (size_t)(k0 + r) * D_DIM + n0 + bcl, 16);
            }
            cp_commit();
        }

        const __half* Ac = Ab + (kt % NST) * SAH;
        const __half* Bc = Bb + (kt % NST) * SBH;
        #pragma unroll
        for (int kk = 0; kk < KCH; kk += 16) {
            wmma::fragment<wmma::matrix_a, 16, 16, 16, __half, wmma::row_major> af[4];
            wmma::fragment<wmma::matrix_b, 16, 16, 16, __half, wmma::row_major> bf[4];
            #pragma unroll
            for (int i = 0; i < 4; ++i)
                wmma::load_matrix_sync(af[i], Ac + (wrow + i * 16) * AST + kk, AST);
            #pragma unroll
            for (int j = 0; j < 4; ++j)
                wmma::load_matrix_sync(bf[j], Bc + kk * BST + wcol + j * 16, BST);
            #pragma unroll
            for (int i = 0; i < 4; ++i)
                #pragma unroll
                for (int j = 0; j < 4; ++j)
                    wmma::mma_sync(cf[i][j], af[i], bf[j], cf[i][j]);
        }
    }
    __syncthreads();

    // ---- epilogue: bias, fp16 coalesced store to g_ysh ----
    float* patch = (float*)dyn;
    #pragma unroll
    for (int i = 0; i < 4; ++i)
        #pragma unroll
        for (int j = 0; j < 4; ++j)
            wmma::store_matrix_sync(patch + (wrow + i * 16) * 132 + wcol + j * 16,
                                    cf[i][j], 132, wmma::mem_row_major);
    __syncthreads();

    const int ec = (tid & 31) << 2;
    const float4 bv = *(const float4*)(be + n0 + ec);
    #pragma unroll
    for (int k = 0; k < 32; ++k) {
        int r = (tid >> 5) + k * 4;
        float4 v = *(const float4*)(patch + r * 132 + ec);
        v.x += bv.x; v.y += bv.y; v.z += bv.z; v.w += bv.w;
        *(uint2*)(g_ysh + (size_t)(row0 + r) * D_DIM + n0 + ec) = pack4h(v.x, v.y, v.z, v.w);
    }
}

// ---------------- combine: out[t] = w0*ysh[r0] + w1*ysh[r1] (fp32 out) ----------------
__global__ __launch_bounds__(256) void combine_kernel(float* __restrict__ out) {
    int i = blockIdx.x * 256 + threadIdx.x;      // over T*D/4 groups of 4
    int t = i >> 8;                              // D/4 = 256 quads per token
    int c = i & 255;
    int r0 = g_row_of_tk[2 * t], r1 = g_row_of_tk[2 * t + 1];
    float w0 = g_top_w[2 * t],   w1 = g_top_w[2 * t + 1];
    uint2 ua = ((const uint2*)g_ysh)[(size_t)r0 * 256 + c];
    uint2 ub = ((const uint2*)g_ysh)[(size_t)r1 * 256 + c];
    __half2 a01 = *(__half2*)&ua.x, a23 = *(__half2*)&ua.y;
    __half2 b01 = *(__half2*)&ub.x, b23 = *(__half2*)&ub.y;
    float2 fa01 = __half22float2(a01), fa23 = __half22float2(a23);
    float2 fb01 = __half22float2(b01), fb23 = __half22float2(b23);
    float4 o;
    o.x = w0 * fa01.x + w1 * fb01.x;
    o.y = w0 * fa01.y + w1 * fb01.y;
    o.z = w0 * fa23.x + w1 * fb23.x;
    o.w = w0 * fa23.y + w1 * fb23.y;
    ((float4*)out)[i] = o;
}

// ---------------- launch ----------------
extern "C" void kernel_launch(void* const* d_in, const int* in_sizes, int n_in,
                              void* d_out, int out_size) {
    const float* x  = (const float*)d_in[0];
    const float* rw = (const float*)d_in[1];
    const float* rb = (const float*)d_in[2];
    const float* w1 = (const float*)d_in[3];
    const float* b1 = (const float*)d_in[4];
    const float* w2 = (const float*)d_in[5];
    const float* b2 = (const float*)d_in[6];
    float* out = (float*)d_out;

    static int attr_done = 0;
    if (!attr_done) {
        cudaFuncSetAttribute(gemm1_kernel, cudaFuncAttributeMaxDynamicSharedMemorySize, DYN_B);
        cudaFuncSetAttribute(gemm2_kernel, cudaFuncAttributeMaxDynamicSharedMemorySize, DYN_B);
        attr_done = 1;
    }

    init_kernel<<<(PADMAX + 255) / 256, 256>>>();
    router_kernel<<<T_TOK / 8, 256>>>(x, rw, rb);
    offsets_kernel<<<1, 32>>>(out, out_size);
    scatter_kernel<<<(T_TOK + 255) / 256, 256>>>();

    // fp32 -> fp16 operand conversion (dst selected inside kernel, NOT host-passed)
    conv_kernel<<<(T_TOK * D_DIM / 4 + 255) / 256, 256>>>(x,  T_TOK * D_DIM / 4, 0);
    conv_kernel<<<(E_EXP * D_DIM * H_DIM / 4 + 255) / 256, 256>>>(w1, E_EXP * D_DIM * H_DIM / 4, 1);
    conv_kernel<<<(E_EXP * H_DIM * D_DIM / 4 + 255) / 256, 256>>>(w2, E_EXP * H_DIM * D_DIM / 4, 2);

    gemm1_kernel<<<dim3(H_DIM / 128, MT), 128, DYN_B>>>(b1);
    gemm2_kernel<<<dim3(D_DIM / 128, MT), 128, DYN_B>>>(b2);
    combine_kernel<<<T_TOK, 256>>>(out);
}